// round 1
// baseline (speedup 1.0000x reference)
#include <cuda_runtime.h>

// Problem constants
#define TT 16      // chars per word (time steps)
#define NB 4096    // B*S words
#define EE 64      // char embedding dim
#define HH 256     // hidden
#define G4 1024    // 4*H gates
#define VOCAB 262

// ------------------------- device scratch (static, no allocs) -------------------------
__device__ __align__(16) float d_x[TT * NB * EE];        // gathered embeddings [T][N][E]
__device__ __align__(16) float d_Wt_l0[2][320 * G4];     // [dir][k][gatecol]; k<256 = W_hh, k>=256 = W_ih
__device__ __align__(16) float d_Wt_l1[2][512 * G4];     // [dir][k][gatecol]; only W_ih (h_prev = 0)
__device__ __align__(16) float d_Wt_out[512 * HH];       // [k][j] = w_out[j][k]
__device__ __align__(16) float d_h[2][2][NB * HH];       // [dir][pingpong][N*H]
__device__ __align__(16) float d_c[2][NB * HH];          // [dir][N*H]
__device__ __align__(16) float d_h0save[2][NB * HH];     // first-step h of each layer-0 direction
__device__ __align__(16) float d_h1[2][NB * HH];         // layer-1 single-step outputs
__device__ int d_is64;

__device__ __forceinline__ float sigf(float x) { return 1.0f / (1.0f + __expf(-x)); }

// ------------------------- shared GEMM tile core -------------------------
// C[128 rows x 128 cols] += A[128 x K] * W^T, A split into two K-segments
// (seg0 = first SCH*8 k's, seg1 = rest). W stored K-major: W[k*ldw + gcol].
// gcol is the per-thread global weight column for its Bs lane (tid & 127).
template <int TCH, int SCH>
__device__ __forceinline__ void gemm_tile(
    const float* __restrict__ seg0, int ld0,
    const float* __restrict__ seg1, int ld1,
    const float* __restrict__ W, int ldw, int gcol,
    int m0, float* As, float* Bs, float acc[8][8])
{
    const int tid   = threadIdx.x;
    const int arow  = tid >> 1;     // 0..127
    const int apart = tid & 1;      // which half of the 8-wide k chunk
    const int bcc   = tid & 127;    // Bs column lane
    const int bk0   = tid >> 7;     // 0..1
    const int tx    = tid & 15;
    const int ty    = tid >> 4;

    const float* a_base0 = seg0 + (size_t)(m0 + arow) * ld0 + apart * 4;
    const float* a_base1 = seg1 + (size_t)(m0 + arow) * ld1 + apart * 4;
    const float* w_base  = W + gcol;

#pragma unroll 1
    for (int kc = 0; kc < TCH; ++kc) {
        const int k0 = kc * 8;
        float4 av;
        if (kc < SCH) av = *(const float4*)(a_base0 + k0);
        else          av = *(const float4*)(a_base1 + (k0 - SCH * 8));
        float bv0 = w_base[(size_t)(k0 + bk0 + 0) * ldw];
        float bv1 = w_base[(size_t)(k0 + bk0 + 2) * ldw];
        float bv2 = w_base[(size_t)(k0 + bk0 + 4) * ldw];
        float bv3 = w_base[(size_t)(k0 + bk0 + 6) * ldw];
        __syncthreads();
        As[(apart * 4 + 0) * 128 + arow] = av.x;
        As[(apart * 4 + 1) * 128 + arow] = av.y;
        As[(apart * 4 + 2) * 128 + arow] = av.z;
        As[(apart * 4 + 3) * 128 + arow] = av.w;
        Bs[(bk0 + 0) * 128 + bcc] = bv0;
        Bs[(bk0 + 2) * 128 + bcc] = bv1;
        Bs[(bk0 + 4) * 128 + bcc] = bv2;
        Bs[(bk0 + 6) * 128 + bcc] = bv3;
        __syncthreads();
#pragma unroll
        for (int kk = 0; kk < 8; ++kk) {
            float4 a0 = *(const float4*)&As[kk * 128 + ty * 8];
            float4 a1 = *(const float4*)&As[kk * 128 + ty * 8 + 4];
            float4 b0 = *(const float4*)&Bs[kk * 128 + tx * 8];
            float4 b1 = *(const float4*)&Bs[kk * 128 + tx * 8 + 4];
            float a[8] = {a0.x, a0.y, a0.z, a0.w, a1.x, a1.y, a1.z, a1.w};
            float b[8] = {b0.x, b0.y, b0.z, b0.w, b1.x, b1.y, b1.z, b1.w};
#pragma unroll
            for (int r = 0; r < 8; ++r)
#pragma unroll
                for (int c = 0; c < 8; ++c)
                    acc[r][c] = fmaf(a[r], b[c], acc[r][c]);
        }
    }
    __syncthreads();  // protect smem before epilogue reuse
}

// ------------------------- layer-0 fused LSTM step -------------------------
// grid (8 j-tiles, 32 m-tiles, 2 dirs). Computes 128 rows x 32 j, all 4 gates,
// fused sigmoid/tanh + cell update. K = 320 (256 h_prev + 64 x_t).
__global__ void __launch_bounds__(256, 2) lstm_l0_step_kernel(
    const float* __restrict__ bias_f, const float* __restrict__ bias_b, int s)
{
    extern __shared__ float smem[];
    float* As = smem;
    float* Bs = smem + 8 * 128;
    const int tid = threadIdx.x;
    const int j0  = blockIdx.x * 32;
    const int m0  = blockIdx.y * 128;
    const int dir = blockIdx.z;

    const int cc   = tid & 127;
    const int gcol = (cc >> 5) * HH + j0 + (cc & 31);  // gate*256 + j

    const float* seg0 = d_h[dir][s & 1];
    const int xt      = dir ? (TT - 1 - s) : s;
    const float* seg1 = d_x + (size_t)xt * NB * EE;
    const float* W    = d_Wt_l0[dir];

    float acc[8][8];
#pragma unroll
    for (int r = 0; r < 8; ++r)
#pragma unroll
        for (int c = 0; c < 8; ++c) acc[r][c] = 0.0f;

    gemm_tile<40, 32>(seg0, HH, seg1, EE, W, G4, gcol, m0, As, Bs, acc);

    // stage gates to smem so each thread can gather i/f/g/o for one (n, j)
    float* Cs = smem;
    const int tx = tid & 15, ty = tid >> 4;
#pragma unroll
    for (int r = 0; r < 8; ++r) {
        float4* dst = (float4*)&Cs[(ty * 8 + r) * 128 + tx * 8];
        dst[0] = make_float4(acc[r][0], acc[r][1], acc[r][2], acc[r][3]);
        dst[1] = make_float4(acc[r][4], acc[r][5], acc[r][6], acc[r][7]);
    }
    __syncthreads();

    const float* bias = dir ? bias_b : bias_f;
    float* cst   = d_c[dir];
    float* hnext = d_h[dir][(s + 1) & 1];
    float* hsv   = d_h0save[dir];
    const bool save0 = (s == 0);
#pragma unroll
    for (int it = 0; it < 16; ++it) {
        int p = tid + it * 256;
        int row = p >> 5, jj = p & 31;
        int j = j0 + jj;
        float gi = Cs[row * 128 + jj]           + bias[j];
        float gf = Cs[row * 128 + 32 + jj]      + bias[HH + j];
        float gg = Cs[row * 128 + 64 + jj]      + bias[2 * HH + j];
        float go = Cs[row * 128 + 96 + jj]      + bias[3 * HH + j];
        int off = (m0 + row) * HH + j;
        float cn = sigf(gf) * cst[off] + sigf(gi) * tanhf(gg);
        float h  = sigf(go) * tanhf(cn);
        cst[off]   = cn;
        hnext[off] = h;
        if (save0) hsv[off] = h;
    }
}

// ------------------------- layer-1 single step (h_prev = 0) -------------------------
__global__ void __launch_bounds__(256, 2) lstm_l1_kernel(
    const float* __restrict__ bias_f, const float* __restrict__ bias_b)
{
    extern __shared__ float smem[];
    float* As = smem;
    float* Bs = smem + 8 * 128;
    const int tid = threadIdx.x;
    const int j0  = blockIdx.x * 32;
    const int m0  = blockIdx.y * 128;
    const int z   = blockIdx.z;  // 0 = fwd@t0, 1 = bwd@t(T-1)

    const int cc   = tid & 127;
    const int gcol = (cc >> 5) * HH + j0 + (cc & 31);

    const float* seg0 = z ? d_h[0][0]     : d_h0save[0];  // hf_final | hf0
    const float* seg1 = z ? d_h0save[1]   : d_h[1][0];    // hb0      | hb_final
    const float* W    = d_Wt_l1[z];

    float acc[8][8];
#pragma unroll
    for (int r = 0; r < 8; ++r)
#pragma unroll
        for (int c = 0; c < 8; ++c) acc[r][c] = 0.0f;

    gemm_tile<64, 32>(seg0, HH, seg1, HH, W, G4, gcol, m0, As, Bs, acc);

    float* Cs = smem;
    const int tx = tid & 15, ty = tid >> 4;
#pragma unroll
    for (int r = 0; r < 8; ++r) {
        float4* dst = (float4*)&Cs[(ty * 8 + r) * 128 + tx * 8];
        dst[0] = make_float4(acc[r][0], acc[r][1], acc[r][2], acc[r][3]);
        dst[1] = make_float4(acc[r][4], acc[r][5], acc[r][6], acc[r][7]);
    }
    __syncthreads();

    const float* bias = z ? bias_b : bias_f;
    float* hout = d_h1[z];
#pragma unroll
    for (int it = 0; it < 16; ++it) {
        int p = tid + it * 256;
        int row = p >> 5, jj = p & 31;
        int j = j0 + jj;
        float gi = Cs[row * 128 + jj]      + bias[j];
        float gg = Cs[row * 128 + 64 + jj] + bias[2 * HH + j];
        float go = Cs[row * 128 + 96 + jj] + bias[3 * HH + j];
        // c_prev = 0 -> c = sig(i)*tanh(g)
        float cn = sigf(gi) * tanhf(gg);
        hout[(m0 + row) * HH + j] = sigf(go) * tanhf(cn);
    }
}

// ------------------------- output projection -------------------------
// out[n][j] = b_out[j] + h1f0[n] . w_out[j][0:256] + h1bT[n] . w_out[j][256:512]
__global__ void __launch_bounds__(256, 2) proj_kernel(
    const float* __restrict__ b_out, float* __restrict__ out)
{
    extern __shared__ float smem[];
    float* As = smem;
    float* Bs = smem + 8 * 128;
    const int tid = threadIdx.x;
    const int c0  = blockIdx.x * 128;
    const int m0  = blockIdx.y * 128;
    const int gcol = c0 + (tid & 127);

    float acc[8][8];
#pragma unroll
    for (int r = 0; r < 8; ++r)
#pragma unroll
        for (int c = 0; c < 8; ++c) acc[r][c] = 0.0f;

    gemm_tile<64, 32>(d_h1[0], HH, d_h1[1], HH, d_Wt_out, HH, gcol, m0, As, Bs, acc);

    const int tx = tid & 15, ty = tid >> 4;
#pragma unroll
    for (int r = 0; r < 8; ++r) {
        int n = m0 + ty * 8 + r;
#pragma unroll
        for (int c = 0; c < 8; ++c) {
            int j = c0 + tx * 8 + c;
            out[(size_t)n * HH + j] = acc[r][c] + b_out[j];
        }
    }
}

// ------------------------- prep kernels -------------------------
__global__ void detect_dtype_kernel(const int* __restrict__ ids32)
{
    if (threadIdx.x == 0 && blockIdx.x == 0) {
        int all0 = 1;
        for (int i = 0; i < 64; ++i)
            if (ids32[2 * i + 1] != 0) { all0 = 0; break; }
        d_is64 = all0;  // random ids in [0,262): odd words all-zero <=> int64 storage
    }
}

__global__ void zero_state_kernel()
{
    int idx = blockIdx.x * blockDim.x + threadIdx.x;
    float4 z = make_float4(0.f, 0.f, 0.f, 0.f);
    if (idx < (2 * 2 * NB * HH) / 4) ((float4*)d_h)[idx] = z;
    if (idx < (2 * NB * HH) / 4)     ((float4*)d_c)[idx] = z;
}

__global__ void gather_emb_kernel(const void* __restrict__ idsv,
                                  const float4* __restrict__ emb4)
{
    int idx = blockIdx.x * blockDim.x + threadIdx.x;  // (t*N + n)*16 + v
    if (idx >= TT * NB * (EE / 4)) return;
    int v = idx & 15;
    int n = (idx >> 4) & (NB - 1);
    int t = idx >> 16;
    int id;
    if (d_is64) id = (int)((const long long*)idsv)[n * TT + t];
    else        id = ((const int*)idsv)[n * TT + t];
    id = min(max(id, 0), VOCAB - 1);
    ((float4*)d_x)[idx] = emb4[id * (EE / 4) + v];
}

__global__ void pack_l0_kernel(const float* __restrict__ wih_f, const float* __restrict__ whh_f,
                               const float* __restrict__ wih_b, const float* __restrict__ whh_b)
{
    int idx = blockIdx.x * blockDim.x + threadIdx.x;
    if (idx >= 2 * 320 * G4) return;
    int dir = idx / (320 * G4);
    int rem = idx % (320 * G4);
    int k = rem / G4, col = rem % G4;
    const float* wih = dir ? wih_b : wih_f;
    const float* whh = dir ? whh_b : whh_f;
    float v = (k < HH) ? whh[(size_t)col * HH + k] : wih[(size_t)col * EE + (k - HH)];
    d_Wt_l0[dir][k * G4 + col] = v;
}

__global__ void pack_l1_kernel(const float* __restrict__ wih_f, const float* __restrict__ wih_b)
{
    int idx = blockIdx.x * blockDim.x + threadIdx.x;
    if (idx >= 2 * 512 * G4) return;
    int dir = idx / (512 * G4);
    int rem = idx % (512 * G4);
    int k = rem / G4, col = rem % G4;
    const float* wih = dir ? wih_b : wih_f;
    d_Wt_l1[dir][k * G4 + col] = wih[(size_t)col * 512 + k];
}

__global__ void pack_out_kernel(const float* __restrict__ w_out)
{
    int idx = blockIdx.x * blockDim.x + threadIdx.x;
    if (idx >= 512 * HH) return;
    int k = idx / HH, j = idx % HH;
    d_Wt_out[k * HH + j] = w_out[(size_t)j * 512 + k];
}

// ------------------------- entry point -------------------------
extern "C" void kernel_launch(void* const* d_in, const int* in_sizes, int n_in,
                              void* d_out, int out_size)
{
    const void*  ids   = d_in[0];
    const float* emb   = (const float*)d_in[1];
    const float* wih0f = (const float*)d_in[2];
    const float* whh0f = (const float*)d_in[3];
    const float* b0f   = (const float*)d_in[4];
    const float* wih0b = (const float*)d_in[5];
    const float* whh0b = (const float*)d_in[6];
    const float* b0b   = (const float*)d_in[7];
    const float* wih1f = (const float*)d_in[8];
    // d_in[9]  = w_hh_l1f  (unused: layer-1 h_prev == 0)
    const float* b1f   = (const float*)d_in[10];
    const float* wih1b = (const float*)d_in[11];
    // d_in[12] = w_hh_l1b  (unused)
    const float* b1b   = (const float*)d_in[13];
    const float* wout  = (const float*)d_in[14];
    const float* bout  = (const float*)d_in[15];
    float* out = (float*)d_out;

    cudaFuncSetAttribute(lstm_l0_step_kernel, cudaFuncAttributeMaxDynamicSharedMemorySize, 65536);
    cudaFuncSetAttribute(lstm_l1_kernel,      cudaFuncAttributeMaxDynamicSharedMemorySize, 65536);

    detect_dtype_kernel<<<1, 32>>>((const int*)ids);
    zero_state_kernel<<<4096, 256>>>();
    gather_emb_kernel<<<(TT * NB * (EE / 4) + 255) / 256, 256>>>(ids, (const float4*)emb);
    pack_l0_kernel<<<(2 * 320 * G4 + 255) / 256, 256>>>(wih0f, whh0f, wih0b, whh0b);
    pack_l1_kernel<<<(2 * 512 * G4 + 255) / 256, 256>>>(wih1f, wih1b);
    pack_out_kernel<<<(512 * HH + 255) / 256, 256>>>(wout);

    for (int s = 0; s < TT; ++s)
        lstm_l0_step_kernel<<<dim3(8, 32, 2), 256, 65536>>>(b0f, b0b, s);

    lstm_l1_kernel<<<dim3(8, 32, 2), 256, 65536>>>(b1f, b1b);
    proj_kernel<<<dim3(2, 32, 1), 256, 8192>>>(bout, out);
}

// round 2
// speedup vs baseline: 1.0004x; 1.0004x over previous
#include <cuda_runtime.h>

// Problem constants
#define TT 16      // chars per word (time steps)
#define NB 4096    // B*S words
#define EE 64      // char embedding dim
#define HH 256     // hidden
#define G4 1024    // 4*H gates
#define VOCAB 262

// ------------------------- device scratch (static, no allocs) -------------------------
__device__ __align__(16) float d_x[TT * NB * EE];        // gathered embeddings [T][N][E]
__device__ __align__(16) float d_Wt_l0[2][320 * G4];     // [dir][k][gatecol]; k<256 = W_hh, k>=256 = W_ih
__device__ __align__(16) float d_Wt_l1[2][512 * G4];     // [dir][k][gatecol]; only W_ih (h_prev = 0)
__device__ __align__(16) float d_Wt_out[512 * HH];       // [k][j] = w_out[j][k]
__device__ __align__(16) float d_h[2][2][NB * HH];       // [dir][pingpong][N*H]
__device__ __align__(16) float d_c[2][NB * HH];          // [dir][N*H]
__device__ __align__(16) float d_h0save[2][NB * HH];     // first-step h of each layer-0 direction
__device__ __align__(16) float d_h1[2][NB * HH];         // layer-1 single-step outputs
__device__ int d_is64;

__device__ __forceinline__ float sigf(float x) { return 1.0f / (1.0f + __expf(-x)); }

// ------------------------- shared GEMM tile core -------------------------
// C[128 rows x 128 cols] += A[128 x K] * W^T, A split into two K-segments
// (seg0 = first SCH*8 k's, seg1 = rest). W stored K-major: W[k*ldw + gcol].
// gcol is the per-thread global weight column for its Bs lane (tid & 127).
template <int TCH, int SCH>
__device__ __forceinline__ void gemm_tile(
    const float* __restrict__ seg0, int ld0,
    const float* __restrict__ seg1, int ld1,
    const float* __restrict__ W, int ldw, int gcol,
    int m0, float* As, float* Bs, float acc[8][8])
{
    const int tid   = threadIdx.x;
    const int arow  = tid >> 1;     // 0..127
    const int apart = tid & 1;      // which half of the 8-wide k chunk
    const int bcc   = tid & 127;    // Bs column lane
    const int bk0   = tid >> 7;     // 0..1
    const int tx    = tid & 15;
    const int ty    = tid >> 4;

    const float* a_base0 = seg0 + (size_t)(m0 + arow) * ld0 + apart * 4;
    const float* a_base1 = seg1 + (size_t)(m0 + arow) * ld1 + apart * 4;
    const float* w_base  = W + gcol;

#pragma unroll 1
    for (int kc = 0; kc < TCH; ++kc) {
        const int k0 = kc * 8;
        float4 av;
        if (kc < SCH) av = *(const float4*)(a_base0 + k0);
        else          av = *(const float4*)(a_base1 + (k0 - SCH * 8));
        float bv0 = w_base[(size_t)(k0 + bk0 + 0) * ldw];
        float bv1 = w_base[(size_t)(k0 + bk0 + 2) * ldw];
        float bv2 = w_base[(size_t)(k0 + bk0 + 4) * ldw];
        float bv3 = w_base[(size_t)(k0 + bk0 + 6) * ldw];
        __syncthreads();
        As[(apart * 4 + 0) * 128 + arow] = av.x;
        As[(apart * 4 + 1) * 128 + arow] = av.y;
        As[(apart * 4 + 2) * 128 + arow] = av.z;
        As[(apart * 4 + 3) * 128 + arow] = av.w;
        Bs[(bk0 + 0) * 128 + bcc] = bv0;
        Bs[(bk0 + 2) * 128 + bcc] = bv1;
        Bs[(bk0 + 4) * 128 + bcc] = bv2;
        Bs[(bk0 + 6) * 128 + bcc] = bv3;
        __syncthreads();
#pragma unroll
        for (int kk = 0; kk < 8; ++kk) {
            float4 a0 = *(const float4*)&As[kk * 128 + ty * 8];
            float4 a1 = *(const float4*)&As[kk * 128 + ty * 8 + 4];
            float4 b0 = *(const float4*)&Bs[kk * 128 + tx * 8];
            float4 b1 = *(const float4*)&Bs[kk * 128 + tx * 8 + 4];
            float a[8] = {a0.x, a0.y, a0.z, a0.w, a1.x, a1.y, a1.z, a1.w};
            float b[8] = {b0.x, b0.y, b0.z, b0.w, b1.x, b1.y, b1.z, b1.w};
#pragma unroll
            for (int r = 0; r < 8; ++r)
#pragma unroll
                for (int c = 0; c < 8; ++c)
                    acc[r][c] = fmaf(a[r], b[c], acc[r][c]);
        }
    }
    __syncthreads();  // protect smem before epilogue reuse
}

// ------------------------- layer-0 fused LSTM step -------------------------
// grid (8 j-tiles, 32 m-tiles, 2 dirs). Computes 128 rows x 32 j, all 4 gates,
// fused sigmoid/tanh + cell update. K = 320 (256 h_prev + 64 x_t).
__global__ void __launch_bounds__(256, 2) lstm_l0_step_kernel(
    const float* __restrict__ bias_f, const float* __restrict__ bias_b, int s)
{
    extern __shared__ float smem[];
    float* As = smem;
    float* Bs = smem + 8 * 128;
    const int tid = threadIdx.x;
    const int j0  = blockIdx.x * 32;
    const int m0  = blockIdx.y * 128;
    const int dir = blockIdx.z;

    const int cc   = tid & 127;
    const int gcol = (cc >> 5) * HH + j0 + (cc & 31);  // gate*256 + j

    const float* seg0 = d_h[dir][s & 1];
    const int xt      = dir ? (TT - 1 - s) : s;
    const float* seg1 = d_x + (size_t)xt * NB * EE;
    const float* W    = d_Wt_l0[dir];

    float acc[8][8];
#pragma unroll
    for (int r = 0; r < 8; ++r)
#pragma unroll
        for (int c = 0; c < 8; ++c) acc[r][c] = 0.0f;

    gemm_tile<40, 32>(seg0, HH, seg1, EE, W, G4, gcol, m0, As, Bs, acc);

    // stage gates to smem so each thread can gather i/f/g/o for one (n, j)
    float* Cs = smem;
    const int tx = tid & 15, ty = tid >> 4;
#pragma unroll
    for (int r = 0; r < 8; ++r) {
        float4* dst = (float4*)&Cs[(ty * 8 + r) * 128 + tx * 8];
        dst[0] = make_float4(acc[r][0], acc[r][1], acc[r][2], acc[r][3]);
        dst[1] = make_float4(acc[r][4], acc[r][5], acc[r][6], acc[r][7]);
    }
    __syncthreads();

    const float* bias = dir ? bias_b : bias_f;
    float* cst   = d_c[dir];
    float* hnext = d_h[dir][(s + 1) & 1];
    float* hsv   = d_h0save[dir];
    const bool save0 = (s == 0);
#pragma unroll
    for (int it = 0; it < 16; ++it) {
        int p = tid + it * 256;
        int row = p >> 5, jj = p & 31;
        int j = j0 + jj;
        float gi = Cs[row * 128 + jj]           + bias[j];
        float gf = Cs[row * 128 + 32 + jj]      + bias[HH + j];
        float gg = Cs[row * 128 + 64 + jj]      + bias[2 * HH + j];
        float go = Cs[row * 128 + 96 + jj]      + bias[3 * HH + j];
        int off = (m0 + row) * HH + j;
        float cn = sigf(gf) * cst[off] + sigf(gi) * tanhf(gg);
        float h  = sigf(go) * tanhf(cn);
        cst[off]   = cn;
        hnext[off] = h;
        if (save0) hsv[off] = h;
    }
}

// ------------------------- layer-1 single step (h_prev = 0) -------------------------
__global__ void __launch_bounds__(256, 2) lstm_l1_kernel(
    const float* __restrict__ bias_f, const float* __restrict__ bias_b)
{
    extern __shared__ float smem[];
    float* As = smem;
    float* Bs = smem + 8 * 128;
    const int tid = threadIdx.x;
    const int j0  = blockIdx.x * 32;
    const int m0  = blockIdx.y * 128;
    const int z   = blockIdx.z;  // 0 = fwd@t0, 1 = bwd@t(T-1)

    const int cc   = tid & 127;
    const int gcol = (cc >> 5) * HH + j0 + (cc & 31);

    const float* seg0 = z ? d_h[0][0]     : d_h0save[0];  // hf_final | hf0
    const float* seg1 = z ? d_h0save[1]   : d_h[1][0];    // hb0      | hb_final
    const float* W    = d_Wt_l1[z];

    float acc[8][8];
#pragma unroll
    for (int r = 0; r < 8; ++r)
#pragma unroll
        for (int c = 0; c < 8; ++c) acc[r][c] = 0.0f;

    gemm_tile<64, 32>(seg0, HH, seg1, HH, W, G4, gcol, m0, As, Bs, acc);

    float* Cs = smem;
    const int tx = tid & 15, ty = tid >> 4;
#pragma unroll
    for (int r = 0; r < 8; ++r) {
        float4* dst = (float4*)&Cs[(ty * 8 + r) * 128 + tx * 8];
        dst[0] = make_float4(acc[r][0], acc[r][1], acc[r][2], acc[r][3]);
        dst[1] = make_float4(acc[r][4], acc[r][5], acc[r][6], acc[r][7]);
    }
    __syncthreads();

    const float* bias = z ? bias_b : bias_f;
    float* hout = d_h1[z];
#pragma unroll
    for (int it = 0; it < 16; ++it) {
        int p = tid + it * 256;
        int row = p >> 5, jj = p & 31;
        int j = j0 + jj;
        float gi = Cs[row * 128 + jj]      + bias[j];
        float gg = Cs[row * 128 + 64 + jj] + bias[2 * HH + j];
        float go = Cs[row * 128 + 96 + jj] + bias[3 * HH + j];
        // c_prev = 0 -> c = sig(i)*tanh(g)
        float cn = sigf(gi) * tanhf(gg);
        hout[(m0 + row) * HH + j] = sigf(go) * tanhf(cn);
    }
}

// ------------------------- output projection -------------------------
// out[n][j] = b_out[j] + h1f0[n] . w_out[j][0:256] + h1bT[n] . w_out[j][256:512]
__global__ void __launch_bounds__(256, 2) proj_kernel(
    const float* __restrict__ b_out, float* __restrict__ out)
{
    extern __shared__ float smem[];
    float* As = smem;
    float* Bs = smem + 8 * 128;
    const int tid = threadIdx.x;
    const int c0  = blockIdx.x * 128;
    const int m0  = blockIdx.y * 128;
    const int gcol = c0 + (tid & 127);

    float acc[8][8];
#pragma unroll
    for (int r = 0; r < 8; ++r)
#pragma unroll
        for (int c = 0; c < 8; ++c) acc[r][c] = 0.0f;

    gemm_tile<64, 32>(d_h1[0], HH, d_h1[1], HH, d_Wt_out, HH, gcol, m0, As, Bs, acc);

    const int tx = tid & 15, ty = tid >> 4;
#pragma unroll
    for (int r = 0; r < 8; ++r) {
        int n = m0 + ty * 8 + r;
#pragma unroll
        for (int c = 0; c < 8; ++c) {
            int j = c0 + tx * 8 + c;
            out[(size_t)n * HH + j] = acc[r][c] + b_out[j];
        }
    }
}

// ------------------------- prep kernels -------------------------
__global__ void detect_dtype_kernel(const int* __restrict__ ids32)
{
    if (threadIdx.x == 0 && blockIdx.x == 0) {
        int all0 = 1;
        for (int i = 0; i < 64; ++i)
            if (ids32[2 * i + 1] != 0) { all0 = 0; break; }
        d_is64 = all0;  // random ids in [0,262): odd words all-zero <=> int64 storage
    }
}

__global__ void zero_state_kernel()
{
    int idx = blockIdx.x * blockDim.x + threadIdx.x;
    float4 z = make_float4(0.f, 0.f, 0.f, 0.f);
    if (idx < (2 * 2 * NB * HH) / 4) ((float4*)d_h)[idx] = z;
    if (idx < (2 * NB * HH) / 4)     ((float4*)d_c)[idx] = z;
}

__global__ void gather_emb_kernel(const void* __restrict__ idsv,
                                  const float4* __restrict__ emb4)
{
    int idx = blockIdx.x * blockDim.x + threadIdx.x;  // (t*N + n)*16 + v
    if (idx >= TT * NB * (EE / 4)) return;
    int v = idx & 15;
    int n = (idx >> 4) & (NB - 1);
    int t = idx >> 16;
    int id;
    if (d_is64) id = (int)((const long long*)idsv)[n * TT + t];
    else        id = ((const int*)idsv)[n * TT + t];
    id = min(max(id, 0), VOCAB - 1);
    ((float4*)d_x)[idx] = emb4[id * (EE / 4) + v];
}

__global__ void pack_l0_kernel(const float* __restrict__ wih_f, const float* __restrict__ whh_f,
                               const float* __restrict__ wih_b, const float* __restrict__ whh_b)
{
    int idx = blockIdx.x * blockDim.x + threadIdx.x;
    if (idx >= 2 * 320 * G4) return;
    int dir = idx / (320 * G4);
    int rem = idx % (320 * G4);
    int k = rem / G4, col = rem % G4;
    const float* wih = dir ? wih_b : wih_f;
    const float* whh = dir ? whh_b : whh_f;
    float v = (k < HH) ? whh[(size_t)col * HH + k] : wih[(size_t)col * EE + (k - HH)];
    d_Wt_l0[dir][k * G4 + col] = v;
}

__global__ void pack_l1_kernel(const float* __restrict__ wih_f, const float* __restrict__ wih_b)
{
    int idx = blockIdx.x * blockDim.x + threadIdx.x;
    if (idx >= 2 * 512 * G4) return;
    int dir = idx / (512 * G4);
    int rem = idx % (512 * G4);
    int k = rem / G4, col = rem % G4;
    const float* wih = dir ? wih_b : wih_f;
    d_Wt_l1[dir][k * G4 + col] = wih[(size_t)col * 512 + k];
}

__global__ void pack_out_kernel(const float* __restrict__ w_out)
{
    int idx = blockIdx.x * blockDim.x + threadIdx.x;
    if (idx >= 512 * HH) return;
    int k = idx / HH, j = idx % HH;
    d_Wt_out[k * HH + j] = w_out[(size_t)j * 512 + k];
}

// ------------------------- entry point -------------------------
extern "C" void kernel_launch(void* const* d_in, const int* in_sizes, int n_in,
                              void* d_out, int out_size)
{
    const void*  ids   = d_in[0];
    const float* emb   = (const float*)d_in[1];
    const float* wih0f = (const float*)d_in[2];
    const float* whh0f = (const float*)d_in[3];
    const float* b0f   = (const float*)d_in[4];
    const float* wih0b = (const float*)d_in[5];
    const float* whh0b = (const float*)d_in[6];
    const float* b0b   = (const float*)d_in[7];
    const float* wih1f = (const float*)d_in[8];
    // d_in[9]  = w_hh_l1f  (unused: layer-1 h_prev == 0)
    const float* b1f   = (const float*)d_in[10];
    const float* wih1b = (const float*)d_in[11];
    // d_in[12] = w_hh_l1b  (unused)
    const float* b1b   = (const float*)d_in[13];
    const float* wout  = (const float*)d_in[14];
    const float* bout  = (const float*)d_in[15];
    float* out = (float*)d_out;

    cudaFuncSetAttribute(lstm_l0_step_kernel, cudaFuncAttributeMaxDynamicSharedMemorySize, 65536);
    cudaFuncSetAttribute(lstm_l1_kernel,      cudaFuncAttributeMaxDynamicSharedMemorySize, 65536);

    detect_dtype_kernel<<<1, 32>>>((const int*)ids);
    zero_state_kernel<<<4096, 256>>>();
    gather_emb_kernel<<<(TT * NB * (EE / 4) + 255) / 256, 256>>>(ids, (const float4*)emb);
    pack_l0_kernel<<<(2 * 320 * G4 + 255) / 256, 256>>>(wih0f, whh0f, wih0b, whh0b);
    pack_l1_kernel<<<(2 * 512 * G4 + 255) / 256, 256>>>(wih1f, wih1b);
    pack_out_kernel<<<(512 * HH + 255) / 256, 256>>>(wout);

    for (int s = 0; s < TT; ++s)
        lstm_l0_step_kernel<<<dim3(8, 32, 2), 256, 65536>>>(b0f, b0b, s);

    lstm_l1_kernel<<<dim3(8, 32, 2), 256, 65536>>>(b1f, b1b);
    proj_kernel<<<dim3(2, 32, 1), 256, 8192>>>(bout, out);
}

// round 4
// speedup vs baseline: 1.7583x; 1.7576x over previous
#include <cuda_runtime.h>
#include <cuda_bf16.h>
#include <cstdint>

#define TT 16
#define NB 4096
#define HH 256
#define VOCAB 262
#define SMEM_BYTES 66048   // 512 bias + 32KB A + 32KB B

// ------------------------- fragment-layout global images -------------------------
// A-image block (per m128-tile, per K64 chunk) = 2048 uint4 (32KB):
//   word(4B) addr = s4*2048 + mt*256 + lane*8 + split*4 + reg   (s4: k16 slice, mt: m16 tile)
// B-image block (per n128-tile, per K64 chunk) = 2048 uint4 (32KB):
//   word addr = s4*2048 + f*32 + lane*4 + split*2 + reg          (f: n8 tile)
__device__ __align__(16) uint4 g_himg[2*2*32*4*2048];   // [(dir*2+pp)*128 + m128*4 + ch]
__device__ __align__(16) uint4 g_h0img[2*32*4*2048];    // [dir*128 + m128*4 + ch]
__device__ __align__(16) uint4 g_ximg[16*32*2048];      // [t*32 + m128]
__device__ __align__(16) uint4 g_h1img[32*8*2048];      // [m128*8 + ch]
__device__ __align__(16) uint4 g_bl0[2*5*8*2048];       // [(dir*5+c)*8 + nt]
__device__ __align__(16) uint4 g_bl1[2*8*8*2048];       // [(z*8+c)*8 + nt]
__device__ __align__(16) uint4 g_bpj[8*2*2048];         // [c*2 + nt]
__device__ float g_c[2][NB * HH];
__device__ int g_is64;

// ------------------------- helpers -------------------------
__device__ __forceinline__ uint32_t s2u(const void* p){
    uint32_t a;
    asm("{ .reg .u64 t; cvta.to.shared.u64 t, %1; cvt.u32.u64 %0, t; }" : "=r"(a) : "l"(p));
    return a;
}
__device__ __forceinline__ void cp16(uint32_t d, const void* s){
    asm volatile("cp.async.cg.shared.global [%0], [%1], 16;" :: "r"(d), "l"(s));
}
__device__ __forceinline__ void mma4(float d[4], const uint32_t a[4], uint32_t b0, uint32_t b1){
    asm volatile("mma.sync.aligned.m16n8k16.row.col.f32.bf16.bf16.f32 "
        "{%0,%1,%2,%3},{%4,%5,%6,%7},{%8,%9},{%0,%1,%2,%3};"
        : "+f"(d[0]), "+f"(d[1]), "+f"(d[2]), "+f"(d[3])
        : "r"(a[0]), "r"(a[1]), "r"(a[2]), "r"(a[3]), "r"(b0), "r"(b1));
}
__device__ __forceinline__ float sigf(float x){ return 1.0f / (1.0f + __expf(-x)); }
__device__ __forceinline__ uint32_t pack2(float a, float b){
    __nv_bfloat162 t = __floats2bfloat162_rn(a, b);
    return *(uint32_t*)&t;
}
__device__ __forceinline__ float bflo(float v){   // residual after bf16 rounding
    return v - __bfloat162float(__float2bfloat16_rn(v));
}

struct Src { const uint4* a; const uint4* b; };

// ------------------------- GEMM core: 128x128 CTA tile, 8 warps (64x32) -------------
template<int NC, class F>
__device__ __forceinline__ void gemm_core(F srcf, char* sm, float acc[16][4])
{
    const int tid  = threadIdx.x;
    const int lane = tid & 31, warp = tid >> 5;
    const int wm   = warp >> 2, wn = warp & 3;
    const uint32_t smA = s2u(sm + 512);
    const uint32_t smB = s2u(sm + 512 + 32768);

#pragma unroll 1
    for (int c = 0; c < NC; ++c) {
        __syncthreads();                 // previous compute done before overwrite
        Src s = srcf(c);
#pragma unroll
        for (int i = 0; i < 8; ++i) cp16(smA + (i*256 + tid)*16, s.a + i*256 + tid);
#pragma unroll
        for (int i = 0; i < 8; ++i) cp16(smB + (i*256 + tid)*16, s.b + i*256 + tid);
        asm volatile("cp.async.commit_group;\n\tcp.async.wait_group 0;" ::: "memory");
        __syncthreads();

#pragma unroll
        for (int s4 = 0; s4 < 4; ++s4) {
            uint32_t bfr[4][4];
#pragma unroll
            for (int ni = 0; ni < 4; ++ni) {
                uint32_t ba = smB + s4*8192 + (wn*4 + ni)*512 + lane*16;
                asm volatile("ld.shared.v2.b32 {%0,%1}, [%2];"
                    : "=r"(bfr[ni][0]), "=r"(bfr[ni][1]) : "r"(ba));
                asm volatile("ld.shared.v2.b32 {%0,%1}, [%2];"
                    : "=r"(bfr[ni][2]), "=r"(bfr[ni][3]) : "r"(ba + 8));
            }
#pragma unroll
            for (int mi = 0; mi < 4; ++mi) {
                uint32_t aH[4], aL[4];
                uint32_t aa = smA + s4*8192 + (wm*4 + mi)*1024 + lane*32;
                asm volatile("ld.shared.v4.b32 {%0,%1,%2,%3}, [%4];"
                    : "=r"(aH[0]),"=r"(aH[1]),"=r"(aH[2]),"=r"(aH[3]) : "r"(aa));
                asm volatile("ld.shared.v4.b32 {%0,%1,%2,%3}, [%4];"
                    : "=r"(aL[0]),"=r"(aL[1]),"=r"(aL[2]),"=r"(aL[3]) : "r"(aa + 16));
#pragma unroll
                for (int ni = 0; ni < 4; ++ni) {
                    mma4(acc[mi*4+ni], aH, bfr[ni][0], bfr[ni][1]);  // aH*bH
                    mma4(acc[mi*4+ni], aH, bfr[ni][2], bfr[ni][3]);  // aH*bL
                    mma4(acc[mi*4+ni], aL, bfr[ni][0], bfr[ni][1]);  // aL*bH
                }
            }
        }
    }
    __syncthreads();
}

// write h value pair (j even, j+1) into A-fragment image
__device__ __forceinline__ void store_frag_pair(uint32_t* base, int mrow, int k,
                                                uint32_t hi, uint32_t lo)
{
    int chunk = k >> 6, kk = k & 63;
    int s4 = kk >> 4, hp = (kk >> 3) & 1, cpos = (kk >> 1) & 3;
    int mloc = mrow & 127;
    int lane_a = (mloc & 7)*4 + cpos;
    int reg = ((mloc >> 3) & 1) + 2*hp;
    size_t w = (size_t)chunk*8192 + s4*2048 + (mloc >> 4)*256 + lane_a*8 + reg;
    base[w]     = hi;
    base[w + 4] = lo;
}

// ------------------------- layer-0 fused step -------------------------
__global__ void __launch_bounds__(256, 2) l0_step(int s, const float* __restrict__ bf,
                                                  const float* __restrict__ bb)
{
    extern __shared__ char sm[];
    float* bias_s = (float*)sm;
    const int tid = threadIdx.x;
    const int nt = blockIdx.x, m128 = blockIdx.y, dir = blockIdx.z;
    const int pp = s & 1;
    const int xt = dir ? (TT - 1 - s) : s;
    const float* bias = dir ? bb : bf;
    if (tid < 128) bias_s[tid] = bias[(tid >> 5)*256 + nt*32 + (tid & 31)];

    float acc[16][4];
#pragma unroll
    for (int i = 0; i < 16; ++i)
#pragma unroll
        for (int r = 0; r < 4; ++r) acc[i][r] = 0.0f;

    auto srcf = [&](int c) {
        Src r;
        if (c < 4) r.a = g_himg + ((size_t)(dir*2 + pp)*128 + m128*4 + c)*2048;
        else       r.a = g_ximg + ((size_t)xt*32 + m128)*2048;
        r.b = g_bl0 + ((size_t)(dir*5 + c)*8 + nt)*2048;
        return r;
    };
    gemm_core<5>(srcf, sm, acc);

    // -------- fused LSTM pointwise epilogue --------
    const int lane = tid & 31, warp = tid >> 5, wm = warp >> 2, wn = warp & 3;
    const int c2 = lane & 3;
    float* cbase = g_c[dir];
    uint32_t* himg_n = (uint32_t*)g_himg + ((size_t)(dir*2 + (pp^1))*128 + m128*4)*8192;
    uint32_t* h0img_ = (uint32_t*)g_h0img + ((size_t)dir*128 + m128*4)*8192;

#pragma unroll
    for (int mi = 0; mi < 4; ++mi)
#pragma unroll
    for (int ni = 0; ni < 4; ++ni) {
        float* A4 = acc[mi*4+ni];
        float v1 = (c2 & 1) ? A4[0] : A4[2];
        float v2 = (c2 & 1) ? A4[1] : A4[3];
        float r1 = __shfl_xor_sync(~0u, v1, 1);
        float r2 = __shfl_xor_sync(~0u, v2, 1);
        int mrow = m128*128 + wm*64 + mi*16 + (lane >> 2) + ((c2 & 1) ? 8 : 0);
        float gi, gf, gg, go;
        if ((c2 & 1) == 0) { gi = A4[0]; gf = A4[1]; gg = r1;   go = r2;   }
        else               { gi = r1;   gf = r2;    gg = A4[2]; go = A4[3]; }
        int jj = (wn*4 + ni)*2 + (c2 >> 1);
        gi += bias_s[jj]; gf += bias_s[32 + jj]; gg += bias_s[64 + jj]; go += bias_s[96 + jj];
        int j = nt*32 + jj;               // j even for c2<2, odd for c2>=2
        float2 cp = make_float2(0.f, 0.f);
        if ((c2 & 2) == 0) cp = *(const float2*)&cbase[(size_t)mrow*HH + j];
        float ty  = __shfl_xor_sync(~0u, cp.y, 2);
        float myc = (c2 & 2) ? ty : cp.x;
        float cn  = sigf(gf)*myc + sigf(gi)*tanhf(gg);
        float h   = sigf(go)*tanhf(cn);
        float cn_o = __shfl_xor_sync(~0u, cn, 2);
        float h_o  = __shfl_xor_sync(~0u, h, 2);
        if ((c2 & 2) == 0) {
            *(float2*)&cbase[(size_t)mrow*HH + j] = make_float2(cn, cn_o);
            uint32_t hi = pack2(h, h_o);
            uint32_t lo = pack2(bflo(h), bflo(h_o));
            store_frag_pair(himg_n, mrow, j, hi, lo);
            if (s == 0) store_frag_pair(h0img_, mrow, j, hi, lo);
        }
    }
}

// ------------------------- layer-1 single step (h_prev = c_prev = 0) -----------------
__global__ void __launch_bounds__(256, 2) l1_step(const float* __restrict__ bf,
                                                  const float* __restrict__ bb)
{
    extern __shared__ char sm[];
    float* bias_s = (float*)sm;
    const int tid = threadIdx.x;
    const int nt = blockIdx.x, m128 = blockIdx.y, z = blockIdx.z;
    const float* bias = z ? bb : bf;
    if (tid < 128) bias_s[tid] = bias[(tid >> 5)*256 + nt*32 + (tid & 31)];

    float acc[16][4];
#pragma unroll
    for (int i = 0; i < 16; ++i)
#pragma unroll
        for (int r = 0; r < 4; ++r) acc[i][r] = 0.0f;

    auto srcf = [&](int c) {
        Src r; int cc = c & 3;
        if ((c < 4) == (z == 0))
            r.a = g_h0img + ((size_t)z*128 + m128*4 + cc)*2048;        // h0save[dir=z]
        else
            r.a = g_himg + ((size_t)((1 - z)*2 + 0)*128 + m128*4 + cc)*2048; // final h, dir=1-z
        r.b = g_bl1 + ((size_t)(z*8 + c)*8 + nt)*2048;
        return r;
    };
    gemm_core<8>(srcf, sm, acc);

    const int lane = tid & 31, warp = tid >> 5, wm = warp >> 2, wn = warp & 3;
    const int c2 = lane & 3;
    uint32_t* h1b = (uint32_t*)g_h1img + ((size_t)m128*8 + z*4)*8192;

#pragma unroll
    for (int mi = 0; mi < 4; ++mi)
#pragma unroll
    for (int ni = 0; ni < 4; ++ni) {
        float* A4 = acc[mi*4+ni];
        float v1 = (c2 & 1) ? A4[0] : A4[2];
        float v2 = (c2 & 1) ? A4[1] : A4[3];
        float r1 = __shfl_xor_sync(~0u, v1, 1);
        float r2 = __shfl_xor_sync(~0u, v2, 1);
        int mrow = m128*128 + wm*64 + mi*16 + (lane >> 2) + ((c2 & 1) ? 8 : 0);
        float gi, gg, go;
        if ((c2 & 1) == 0) { gi = A4[0]; gg = r1;   go = r2;   }
        else               { gi = r1;   gg = A4[2]; go = A4[3]; }
        int jj = (wn*4 + ni)*2 + (c2 >> 1);
        gi += bias_s[jj]; gg += bias_s[64 + jj]; go += bias_s[96 + jj];
        int j = nt*32 + jj;
        float cn = sigf(gi)*tanhf(gg);     // c_prev = 0
        float h  = sigf(go)*tanhf(cn);
        float h_o = __shfl_xor_sync(~0u, h, 2);
        if ((c2 & 2) == 0) {
            uint32_t hi = pack2(h, h_o);
            uint32_t lo = pack2(bflo(h), bflo(h_o));
            store_frag_pair(h1b, mrow, j, hi, lo);   // chunk = j>>6 within z*4 base
        }
    }
}

// ------------------------- output projection -------------------------
__global__ void __launch_bounds__(256, 2) proj_k(const float* __restrict__ bo,
                                                 float* __restrict__ out)
{
    extern __shared__ char sm[];
    const int tid = threadIdx.x;
    const int nt = blockIdx.x, m128 = blockIdx.y;

    float acc[16][4];
#pragma unroll
    for (int i = 0; i < 16; ++i)
#pragma unroll
        for (int r = 0; r < 4; ++r) acc[i][r] = 0.0f;

    auto srcf = [&](int c) {
        Src r;
        r.a = g_h1img + ((size_t)m128*8 + c)*2048;
        r.b = g_bpj + ((size_t)c*2 + nt)*2048;
        return r;
    };
    gemm_core<8>(srcf, sm, acc);

    const int lane = tid & 31, warp = tid >> 5, wm = warp >> 2, wn = warp & 3;
#pragma unroll
    for (int mi = 0; mi < 4; ++mi)
#pragma unroll
    for (int ni = 0; ni < 4; ++ni) {
        float* A4 = acc[mi*4+ni];
        int m = m128*128 + wm*64 + mi*16 + (lane >> 2);
        int n = nt*128 + wn*32 + ni*8 + (lane & 3)*2;
        float b0 = __ldg(bo + n), b1 = __ldg(bo + n + 1);
        *(float2*)&out[(size_t)m*HH + n]       = make_float2(A4[0] + b0, A4[1] + b1);
        *(float2*)&out[(size_t)(m + 8)*HH + n] = make_float2(A4[2] + b0, A4[3] + b1);
    }
}

// ------------------------- prep kernels -------------------------
__global__ void detect_k(const int* __restrict__ ids32)
{
    if (threadIdx.x == 0 && blockIdx.x == 0) {
        int all0 = 1;
        for (int i = 0; i < 64; ++i)
            if (ids32[2*i + 1] != 0) { all0 = 0; break; }
        g_is64 = all0;
    }
}

__global__ void zero_k()
{
    size_t i = (size_t)blockIdx.x*blockDim.x + threadIdx.x;
    size_t stride = (size_t)gridDim.x*blockDim.x;
    uint4 z = make_uint4(0,0,0,0);
    const size_t NH = (size_t)2*2*32*4*2048;
    for (size_t p = i; p < NH; p += stride) g_himg[p] = z;
    const size_t NC = (size_t)2*NB*HH/4;
    for (size_t p = i; p < NC; p += stride) ((uint4*)g_c)[p] = z;
}

__global__ void gather_k(const void* __restrict__ idsv, const float* __restrict__ emb)
{
    int idx = blockIdx.x*blockDim.x + threadIdx.x;    // [t][n][epair(32)]
    if (idx >= TT*NB*32) return;
    int ep = idx & 31, n = (idx >> 5) & (NB - 1), t = idx >> 17;
    int id;
    if (g_is64) id = (int)((const long long*)idsv)[n*TT + t];
    else        id = ((const int*)idsv)[n*TT + t];
    id = min(max(id, 0), VOCAB - 1);
    int e = ep*2;
    float2 v = *(const float2*)&emb[(size_t)id*64 + e];
    uint32_t hi = pack2(v.x, v.y);
    uint32_t lo = pack2(bflo(v.x), bflo(v.y));
    uint32_t* base = (uint32_t*)g_ximg + ((size_t)t*32 + (n >> 7))*8192;
    // k = e within the single 64-wide chunk
    int s4 = e >> 4, hp = (e >> 3) & 1, cpos = (e >> 1) & 3;
    int mloc = n & 127;
    int lane_a = (mloc & 7)*4 + cpos;
    int reg = ((mloc >> 3) & 1) + 2*hp;
    size_t w = (size_t)s4*2048 + (mloc >> 4)*256 + lane_a*8 + reg;
    base[w]     = hi;
    base[w + 4] = lo;
}

// B image word decode helper: given w (0..8191) → (k within chunk, n_local)
__device__ __forceinline__ void b_decode(int w, int& kc, int& nloc, int& split)
{
    int s4 = w >> 11, f = (w >> 7) & 15, lane = (w >> 2) & 31, reg = w & 1;
    split = (w >> 1) & 1;
    nloc = f*8 + (lane >> 2);
    kc = s4*16 + (lane & 3)*2 + reg*8;
}

__global__ void pack_l0_k(const float* __restrict__ wf, const float* __restrict__ hf,
                          const float* __restrict__ wb, const float* __restrict__ hb)
{
    int idx = blockIdx.x*blockDim.x + threadIdx.x;
    if (idx >= 2*5*8*8192) return;
    int dir = idx / 327680, r = idx % 327680;
    int c = r >> 16, r2 = r & 65535;
    int nt = r2 >> 13, w = r2 & 8191;
    int kc, nloc, split; b_decode(w, kc, nloc, split);
    int jj = nloc >> 2, g = nloc & 3;
    int col = g*256 + nt*32 + jj;
    int k = c*64 + kc;
    const float* wih = dir ? wb : wf;
    const float* whh = dir ? hb : hf;
    float v0 = (k < 256)   ? whh[(size_t)col*256 + k]       : wih[(size_t)col*64 + k - 256];
    float v1 = (k+1 < 256) ? whh[(size_t)col*256 + k + 1]   : wih[(size_t)col*64 + k + 1 - 256];
    uint32_t val = split ? pack2(bflo(v0), bflo(v1)) : pack2(v0, v1);
    ((uint32_t*)g_bl0)[((size_t)(dir*5 + c)*8 + nt)*8192 + w] = val;
}

__global__ void pack_l1_k(const float* __restrict__ wfz, const float* __restrict__ wbz)
{
    int idx = blockIdx.x*blockDim.x + threadIdx.x;
    if (idx >= 2*8*8*8192) return;
    int z = idx >> 19, r = idx & 524287;
    int c = r >> 16, r2 = r & 65535;
    int nt = r2 >> 13, w = r2 & 8191;
    int kc, nloc, split; b_decode(w, kc, nloc, split);
    int jj = nloc >> 2, g = nloc & 3;
    int col = g*256 + nt*32 + jj;
    int k = c*64 + kc;
    const float* wih = z ? wbz : wfz;
    float v0 = wih[(size_t)col*512 + k];
    float v1 = wih[(size_t)col*512 + k + 1];
    uint32_t val = split ? pack2(bflo(v0), bflo(v1)) : pack2(v0, v1);
    ((uint32_t*)g_bl1)[((size_t)(z*8 + c)*8 + nt)*8192 + w] = val;
}

__global__ void pack_pj_k(const float* __restrict__ wo)
{
    int idx = blockIdx.x*blockDim.x + threadIdx.x;
    if (idx >= 8*2*8192) return;
    int c = idx >> 14, r2 = idx & 16383;
    int nt = r2 >> 13, w = r2 & 8191;
    int kc, nloc, split; b_decode(w, kc, nloc, split);
    int col = nt*128 + nloc;
    int k = c*64 + kc;
    float v0 = wo[(size_t)col*512 + k];
    float v1 = wo[(size_t)col*512 + k + 1];
    uint32_t val = split ? pack2(bflo(v0), bflo(v1)) : pack2(v0, v1);
    ((uint32_t*)g_bpj)[((size_t)c*2 + nt)*8192 + w] = val;
}

// ------------------------- entry point -------------------------
extern "C" void kernel_launch(void* const* d_in, const int* in_sizes, int n_in,
                              void* d_out, int out_size)
{
    const void*  ids   = d_in[0];
    const float* emb   = (const float*)d_in[1];
    const float* wih0f = (const float*)d_in[2];
    const float* whh0f = (const float*)d_in[3];
    const float* b0f   = (const float*)d_in[4];
    const float* wih0b = (const float*)d_in[5];
    const float* whh0b = (const float*)d_in[6];
    const float* b0b   = (const float*)d_in[7];
    const float* wih1f = (const float*)d_in[8];
    const float* b1f   = (const float*)d_in[10];
    const float* wih1b = (const float*)d_in[11];
    const float* b1b   = (const float*)d_in[13];
    const float* wout  = (const float*)d_in[14];
    const float* bout  = (const float*)d_in[15];
    float* out = (float*)d_out;

    cudaFuncSetAttribute(l0_step, cudaFuncAttributeMaxDynamicSharedMemorySize, SMEM_BYTES);
    cudaFuncSetAttribute(l1_step, cudaFuncAttributeMaxDynamicSharedMemorySize, SMEM_BYTES);
    cudaFuncSetAttribute(proj_k,  cudaFuncAttributeMaxDynamicSharedMemorySize, SMEM_BYTES);

    detect_k<<<1, 32>>>((const int*)ids);
    zero_k<<<2048, 256>>>();
    gather_k<<<TT*NB*32/256, 256>>>(ids, emb);
    pack_l0_k<<<(2*5*8*8192)/256, 256>>>(wih0f, whh0f, wih0b, whh0b);
    pack_l1_k<<<(2*8*8*8192)/256, 256>>>(wih1f, wih1b);
    pack_pj_k<<<(8*2*8192)/256, 256>>>(wout);

    for (int s = 0; s < TT; ++s)
        l0_step<<<dim3(8, 32, 2), 256, SMEM_BYTES>>>(s, b0f, b0b);

    l1_step<<<dim3(8, 32, 2), 256, SMEM_BYTES>>>(b1f, b1b);
    proj_k<<<dim3(2, 32, 1), 256, SMEM_BYTES>>>(bout, out);
}